// round 6
// baseline (speedup 1.0000x reference)
#include <cuda_runtime.h>

// Problem constants (fixed shapes per reference)
#define BB   16
#define NN   1024
#define D2H  1024
#define UU   512
#define BN   (BB * NN)      // 16384 rows

#define UCHUNKS 32          // u split for the fold reduction
#define UC_SZ   (UU / UCHUNKS)   // 16 u per chunk

// Scratch (device globals; no allocation allowed)
__device__ float g_part[UCHUNKS * 2 * D2H];  // partial v_h/v_m per u-chunk (256 KB)
__device__ float g_v[2 * D2H];               // [0:1024)=v_h, [1024:2048)=v_m
__device__ float g_c[2];                     // c_h + b_out, c_m
__device__ float g_sH[BN];
__device__ float g_sM[BN];

// ---------------------------------------------------------------------------
// Kernel 1: partial fold. v_h[d] = sum_u W_h[u,d]*w_out[u], split over UCHUNKS.
// Grid: 128 blocks (32 u-chunks x 4 d-blocks) x 256 threads.
// ---------------------------------------------------------------------------
__global__ void fold_part_kernel(const float* __restrict__ W_h,
                                 const float* __restrict__ W_m,
                                 const float* __restrict__ w_out) {
    __shared__ float sw[UC_SZ];
    int tid = threadIdx.x;
    int uc  = blockIdx.x >> 2;           // u-chunk
    int db  = blockIdx.x & 3;            // d-block
    int u0  = uc * UC_SZ;
    if (tid < UC_SZ) sw[tid] = w_out[u0 + tid];
    __syncthreads();

    int d = db * 256 + tid;
    float vh = 0.f, vm = 0.f;
#pragma unroll
    for (int k = 0; k < UC_SZ; k++) {
        int u = u0 + k;
        vh = fmaf(W_h[u * D2H + d], sw[k], vh);
        vm = fmaf(W_m[u * D2H + d], sw[k], vm);
    }
    g_part[uc * 2 * D2H + d]       = vh;
    g_part[uc * 2 * D2H + D2H + d] = vm;
}

// ---------------------------------------------------------------------------
// Kernel 2: reduce partials into g_v, plus the bias constants.
// Grid: 2 blocks x 1024 threads. 256 KB L2-resident read.
// ---------------------------------------------------------------------------
__global__ void reduce_kernel(const float* __restrict__ b_h,
                              const float* __restrict__ b_m,
                              const float* __restrict__ w_out,
                              const float* __restrict__ b_out) {
    int idx = blockIdx.x * 1024 + threadIdx.x;   // 0 .. 2047
    float acc = 0.f;
#pragma unroll
    for (int c = 0; c < UCHUNKS; c++)
        acc += g_part[c * 2 * D2H + idx];
    g_v[idx] = acc;

    if (blockIdx.x == 0 && threadIdx.x < 32) {
        int lane = threadIdx.x;
        float ch = 0.f, cm = 0.f;
        for (int u = lane; u < UU; u += 32) {
            float w = w_out[u];
            ch = fmaf(b_h[u], w, ch);
            cm = fmaf(b_m[u], w, cm);
        }
#pragma unroll
        for (int o = 16; o > 0; o >>= 1) {
            ch += __shfl_down_sync(0xffffffffu, ch, o);
            cm += __shfl_down_sync(0xffffffffu, cm, o);
        }
        if (lane == 0) {
            g_c[0] = ch + b_out[0];
            g_c[1] = cm;
        }
    }
}

// ---------------------------------------------------------------------------
// Kernel 3: dot products, TWO rows per warp for 16 outstanding loads/lane.
//   sH[r] = x[r,:].v_h + c_h(+b_out) ;  sM[r] = x[r,:].v_m + c_m
// 256 threads = 8 warps = 16 rows per block. Grid: 1024 blocks.
// ---------------------------------------------------------------------------
__global__ void dots_kernel(const float* __restrict__ x) {
    __shared__ float4 sv[2 * D2H / 4];   // 8 KB: v_h then v_m as float4
    int tid = threadIdx.x;
    const float4* gv4 = (const float4*)g_v;
    for (int i = tid; i < 2 * D2H / 4; i += 256) sv[i] = gv4[i];
    __syncthreads();

    int warp = tid >> 5, lane = tid & 31;
    int row0 = (blockIdx.x * 8 + warp) * 2;

    const float4* xa = (const float4*)(x + (size_t)row0 * D2H);
    const float4* xb = xa + (D2H / 4);
    float ah0 = 0.f, am0 = 0.f, ah1 = 0.f, am1 = 0.f;
#pragma unroll
    for (int k = 0; k < 8; k++) {
        int i = k * 32 + lane;           // 256 float4 per row, coalesced
        float4 va = xa[i];
        float4 vb = xb[i];
        float4 h  = sv[i];
        float4 m  = sv[256 + i];
        ah0 = fmaf(va.x, h.x, fmaf(va.y, h.y, fmaf(va.z, h.z, fmaf(va.w, h.w, ah0))));
        am0 = fmaf(va.x, m.x, fmaf(va.y, m.y, fmaf(va.z, m.z, fmaf(va.w, m.w, am0))));
        ah1 = fmaf(vb.x, h.x, fmaf(vb.y, h.y, fmaf(vb.z, h.z, fmaf(vb.w, h.w, ah1))));
        am1 = fmaf(vb.x, m.x, fmaf(vb.y, m.y, fmaf(vb.z, m.z, fmaf(vb.w, m.w, am1))));
    }
#pragma unroll
    for (int o = 16; o > 0; o >>= 1) {
        ah0 += __shfl_down_sync(0xffffffffu, ah0, o);
        am0 += __shfl_down_sync(0xffffffffu, am0, o);
        ah1 += __shfl_down_sync(0xffffffffu, ah1, o);
        am1 += __shfl_down_sync(0xffffffffu, am1, o);
    }
    if (lane == 0) {
        float ch = g_c[0], cm = g_c[1];
        g_sH[row0]     = ah0 + ch;
        g_sM[row0]     = am0 + cm;
        g_sH[row0 + 1] = ah1 + ch;
        g_sM[row0 + 1] = am1 + cm;
    }
}

// ---------------------------------------------------------------------------
// Kernel 4: broadcast-add to the [B,N,N] output.
//   out[b,i,j] = sH[b*N+i] + sM[b*N+j]
// 8 output rows per block (8 | 1024 so same batch); each thread holds one
// float4 of sM in registers and writes it into 8 rows.
// Grid: 2048 blocks x 256 threads.
// ---------------------------------------------------------------------------
__global__ void bcast_kernel(float* __restrict__ out) {
    int bi0 = blockIdx.x * 8;            // first of 8 consecutive (b,i) rows
    int b   = bi0 >> 10;                 // N = 1024
    const float4* m4 = (const float4*)g_sM + b * (NN / 4);
    float4 m = m4[threadIdx.x];

    float s[8];
#pragma unroll
    for (int r = 0; r < 8; r++) s[r] = g_sH[bi0 + r];

    float4* o4 = (float4*)out + (size_t)bi0 * (NN / 4) + threadIdx.x;
#pragma unroll
    for (int r = 0; r < 8; r++) {
        o4[r * (NN / 4)] = make_float4(s[r] + m.x, s[r] + m.y,
                                       s[r] + m.z, s[r] + m.w);
    }
}

// ---------------------------------------------------------------------------
extern "C" void kernel_launch(void* const* d_in, const int* in_sizes, int n_in,
                              void* d_out, int out_size) {
    const float* x     = (const float*)d_in[0];
    const float* W_h   = (const float*)d_in[1];
    const float* b_h   = (const float*)d_in[2];
    const float* W_m   = (const float*)d_in[3];
    const float* b_m   = (const float*)d_in[4];
    const float* w_out = (const float*)d_in[5];
    const float* b_out = (const float*)d_in[6];
    float* out = (float*)d_out;

    fold_part_kernel<<<UCHUNKS * 4, 256>>>(W_h, W_m, w_out);
    reduce_kernel<<<2, 1024>>>(b_h, b_m, w_out, b_out);
    dots_kernel<<<BN / 16, 256>>>(x);
    bcast_kernel<<<BN / 8, 256>>>(out);
}